// round 2
// baseline (speedup 1.0000x reference)
#include <cuda_runtime.h>
#include <math.h>

#define L_SEQ 2048
#define B_SZ  16
#define H_DIM 512
#define NS    32
#define BH    (B_SZ*H_DIM)          // 8192
#define LBH   (L_SEQ*B_SZ*H_DIM)    // 16777216

// Scratch (static device globals; no allocations)
__device__ float g_un[LBH];   // normalized input, (L,B,H) layout
__device__ float g_y[LBH];    // post conv+Dskip+gelu, (B,H,L) layout
__device__ float g_rr[H_DIM*NS], g_ri[H_DIM*NS], g_cr[H_DIM*NS], g_ci[H_DIM*NS];

// ---------------------------------------------------------------------------
// K0: per-(h,n) SSM constants:  r = exp(dt*A),  c = 2*C*(r-1)/A  (split re/im)
// ---------------------------------------------------------------------------
__global__ void const_kernel(const float* __restrict__ log_dt,
                             const float* __restrict__ C,
                             const float* __restrict__ log_A_real,
                             const float* __restrict__ A_imag) {
    int idx = blockIdx.x*blockDim.x + threadIdx.x;
    if (idx >= H_DIM*NS) return;
    int h = idx >> 5;
    float dt  = expf(log_dt[h]);
    float Are = -expf(log_A_real[idx]);
    float Aim = A_imag[idx];
    float dre = Are*dt, dim = Aim*dt;
    float er  = expf(dre);
    float rr  = er*cosf(dim), ri = er*sinf(dim);
    // (r - 1) / A
    float nre = rr - 1.f, nim = ri;
    float den = Are*Are + Aim*Aim;
    float qre = (nre*Are + nim*Aim)/den;
    float qim = (nim*Are - nre*Aim)/den;
    float Cre = C[2*idx], Cim = C[2*idx+1];
    float cmre = Cre*qre - Cim*qim;
    float cmim = Cre*qim + Cim*qre;
    g_rr[idx] = rr;  g_ri[idx] = ri;
    g_cr[idx] = 2.f*cmre;          // y_l = cr*s_re + ci*s_im  (= 2*Re(Cm*s))
    g_ci[idx] = -2.f*cmim;
}

// ---------------------------------------------------------------------------
// K1: LayerNorm over H. One warp per (l,b) row (contiguous 512 floats).
// ---------------------------------------------------------------------------
__global__ void ln_kernel(const float* __restrict__ u,
                          const float* __restrict__ lnw,
                          const float* __restrict__ lnb) {
    int warp = (blockIdx.x*blockDim.x + threadIdx.x) >> 5;
    int lane = threadIdx.x & 31;
    if (warp >= L_SEQ*B_SZ) return;
    const float* row = u + (size_t)warp*H_DIM;
    float v[16];
    float s = 0.f, sq = 0.f;
    #pragma unroll
    for (int i = 0; i < 16; i++) {
        float x = row[lane + i*32];
        v[i] = x; s += x; sq += x*x;
    }
    #pragma unroll
    for (int o = 16; o >= 1; o >>= 1) {
        s  += __shfl_xor_sync(0xffffffffu, s,  o);
        sq += __shfl_xor_sync(0xffffffffu, sq, o);
    }
    float mu   = s  * (1.f/H_DIM);
    float var  = sq * (1.f/H_DIM) - mu*mu;
    float rstd = rsqrtf(var + 1e-5f);
    float* orow = g_un + (size_t)warp*H_DIM;
    #pragma unroll
    for (int i = 0; i < 16; i++) {
        int c = lane + i*32;
        orow[c] = (v[i]-mu)*rstd*lnw[c] + lnb[c];
    }
}

// ---------------------------------------------------------------------------
// K2: diagonal-SSM recurrence + D skip + exact GELU.
// One warp per (b,h); lane = state index n (N_HALF == 32).
// Time chunked by 32: lane t preloads u at l0+t, broadcast via shfl.
// ---------------------------------------------------------------------------
__global__ void scan_kernel(const float* __restrict__ D) {
    int warp = (blockIdx.x*blockDim.x + threadIdx.x) >> 5;
    int lane = threadIdx.x & 31;
    if (warp >= BH) return;
    int b = warp / H_DIM;
    int h = warp - b*H_DIM;
    int hi = h*NS + lane;
    float rr = g_rr[hi], ri = g_ri[hi], cr = g_cr[hi], ci = g_ci[hi];
    float Dh = D[h];
    float sre = 0.f, sim = 0.f;
    const float* up = g_un + b*H_DIM + h;          // stride BH over l  (L,B,H)
    float*       yp = g_y + (size_t)warp*L_SEQ;    // (B,H,L) contiguous in l

    float unext = up[(size_t)lane*BH];
    for (int l0 = 0; l0 < L_SEQ; l0 += 32) {
        float uch = unext;
        if (l0 + 32 < L_SEQ) unext = up[(size_t)(l0+32+lane)*BH];
        float yv = 0.f;
        #pragma unroll
        for (int t = 0; t < 32; t++) {
            float uu  = __shfl_sync(0xffffffffu, uch, t);
            float nre = fmaf(rr, sre, fmaf(-ri, sim, uu));
            float nim = fmaf(rr, sim, ri*sre);
            sre = nre; sim = nim;
            float c = fmaf(cr, sre, ci*sim);
            #pragma unroll
            for (int o = 16; o >= 1; o >>= 1)
                c += __shfl_xor_sync(0xffffffffu, c, o);
            if (lane == t) yv = c;
        }
        float yd = yv + Dh*uch;                       // uch is un at this lane's timestep
        float ge = 0.5f*yd*(1.f + erff(yd*0.70710678118f));  // exact GELU
        yp[l0 + lane] = ge;
    }
}

// ---------------------------------------------------------------------------
// K3: fused Conv1d(H->2H,k=1) + GLU + residual + transpose to (L,B,H).
// Per block: 32 h-rows (both a- and g- halves -> 64 W rows) x 64 l-cols, K=512.
// ---------------------------------------------------------------------------
__global__ void gemm_kernel(const float* __restrict__ Wm,
                            const float* __restrict__ bconv,
                            const float* __restrict__ u,
                            float* __restrict__ out) {
    __shared__ float Ws[32][65];    // [k][row(0..63)], pad 65 -> conflict-free
    __shared__ float Ys[32*64];     // [k][l]
    int tid = threadIdx.x;
    int b  = blockIdx.z;
    int h0 = blockIdx.y*32;
    int l0 = blockIdx.x*64;
    int tx = tid & 15, ty = tid >> 4;
    int r0 = ty*2;                  // rows: r0,r0+1 (a) ; r0+32,r0+33 (g)
    float acc[4][4];
    #pragma unroll
    for (int i = 0; i < 4; i++)
        #pragma unroll
        for (int j = 0; j < 4; j++) acc[i][j] = 0.f;

    const float* ybase = g_y + ((size_t)b*H_DIM)*L_SEQ + l0;

    for (int kk = 0; kk < H_DIM; kk += 32) {
        #pragma unroll
        for (int it = 0; it < 8; it++) {            // W tile: 64 rows x 32 k
            int idx = tid + it*256;
            int r = idx >> 5, k = idx & 31;
            int orow = (r < 32) ? (h0 + r) : (H_DIM + h0 + (r - 32));
            Ws[k][r] = Wm[orow*H_DIM + kk + k];
        }
        #pragma unroll
        for (int it = 0; it < 8; it++) {            // Y tile: 32 k x 64 l
            int idx = tid + it*256;
            int k = idx >> 6, c = idx & 63;
            Ys[idx] = ybase[(size_t)(kk + k)*L_SEQ + c];
        }
        __syncthreads();
        #pragma unroll
        for (int k = 0; k < 32; k++) {
            float a0 = Ws[k][r0],    a1 = Ws[k][r0+1];
            float a2 = Ws[k][r0+32], a3 = Ws[k][r0+33];
            float4 bb = reinterpret_cast<const float4*>(Ys + k*64)[tx];
            acc[0][0] = fmaf(a0, bb.x, acc[0][0]);
            acc[0][1] = fmaf(a0, bb.y, acc[0][1]);
            acc[0][2] = fmaf(a0, bb.z, acc[0][2]);
            acc[0][3] = fmaf(a0, bb.w, acc[0][3]);
            acc[1][0] = fmaf(a1, bb.x, acc[1][0]);
            acc[1][1] = fmaf(a1, bb.y, acc[1][1]);
            acc[1][2] = fmaf(a1, bb.z, acc[1][2]);
            acc[1][3] = fmaf(a1, bb.w, acc[1][3]);
            acc[2][0] = fmaf(a2, bb.x, acc[2][0]);
            acc[2][1] = fmaf(a2, bb.y, acc[2][1]);
            acc[2][2] = fmaf(a2, bb.z, acc[2][2]);
            acc[2][3] = fmaf(a2, bb.w, acc[2][3]);
            acc[3][0] = fmaf(a3, bb.x, acc[3][0]);
            acc[3][1] = fmaf(a3, bb.y, acc[3][1]);
            acc[3][2] = fmaf(a3, bb.z, acc[3][2]);
            acc[3][3] = fmaf(a3, bb.w, acc[3][3]);
        }
        __syncthreads();
    }

    int ha0 = h0 + r0, ha1 = h0 + r0 + 1;
    float bA0 = bconv[ha0],       bA1 = bconv[ha1];
    float bG0 = bconv[H_DIM+ha0], bG1 = bconv[H_DIM+ha1];
    #pragma unroll
    for (int j = 0; j < 4; j++) {
        int l = l0 + tx*4 + j;
        size_t base = (size_t)l*BH + (size_t)b*H_DIM;
        float a0v = acc[0][j] + bA0;
        float a1v = acc[1][j] + bA1;
        float g0v = acc[2][j] + bG0;
        float g1v = acc[3][j] + bG1;
        float o0 = a0v * (1.f/(1.f + expf(-g0v)));
        float o1 = a1v * (1.f/(1.f + expf(-g1v)));
        out[base + ha0] = u[base + ha0] + o0;   // residual z = original u
        out[base + ha1] = u[base + ha1] + o1;
    }
}

// ---------------------------------------------------------------------------
extern "C" void kernel_launch(void* const* d_in, const int* in_sizes, int n_in,
                              void* d_out, int out_size) {
    const float* u          = (const float*)d_in[0];
    const float* log_dt     = (const float*)d_in[1];
    const float* C          = (const float*)d_in[2];
    const float* log_A_real = (const float*)d_in[3];
    const float* A_imag     = (const float*)d_in[4];
    const float* D          = (const float*)d_in[5];
    const float* Wm         = (const float*)d_in[6];
    const float* b_conv     = (const float*)d_in[7];
    const float* ln_w       = (const float*)d_in[8];
    const float* ln_b       = (const float*)d_in[9];
    float* out = (float*)d_out;

    const_kernel<<<64, 256>>>(log_dt, C, log_A_real, A_imag);
    ln_kernel<<<(L_SEQ*B_SZ)/8, 256>>>(u, ln_w, ln_b);
    scan_kernel<<<BH/4, 128>>>(D);
    gemm_kernel<<<dim3(L_SEQ/64, H_DIM/32, B_SZ), 256>>>(Wm, b_conv, u, out);
}